// round 1
// baseline (speedup 1.0000x reference)
#include <cuda_runtime.h>
#include <cuda_bf16.h>
#include <math.h>

#define NN 100000
#define EE 1600000
#define CH 64      // NHID
#define NF 128     // NFEAT
#define NC 40      // NCLASS

// ---- scratch (static device globals; no allocation) ----
__device__ float g_h[NN * CH];
__device__ float g_k[NN * CH];
__device__ float g_acc[NN * CH];
__device__ float g_s[NN * CH];     // also holds final 40-col result padded to 64
__device__ int   g_rowptr[NN + 1];
__device__ int   g_cursor[NN];
__device__ int   g_cnt[NN];
__device__ int   g_csrsrc[EE];
__device__ float g_csrw[EE];

// ============================ CSR build ============================
__global__ void k_zero_cnt() {
    int i = blockIdx.x * blockDim.x + threadIdx.x;
    if (i < NN) g_cnt[i] = 0;
}

__global__ void k_hist(const int* __restrict__ tgt) {
    int e = blockIdx.x * blockDim.x + threadIdx.x;
    if (e < EE) atomicAdd(&g_cnt[tgt[e]], 1);
}

// single-block chunked Hillis-Steele scan over NN counts -> exclusive rowptr
__global__ void k_scan() {
    __shared__ int sh[1024];
    __shared__ int soff;
    int tid = threadIdx.x;
    if (tid == 0) soff = 0;
    __syncthreads();
    for (int base = 0; base < NN; base += 1024) {
        int i = base + tid;
        int v = (i < NN) ? g_cnt[i] : 0;
        sh[tid] = v;
        __syncthreads();
        for (int d = 1; d < 1024; d <<= 1) {
            int t = (tid >= d) ? sh[tid - d] : 0;
            __syncthreads();
            sh[tid] += t;
            __syncthreads();
        }
        int off = soff;
        if (i < NN) {
            int ex = off + sh[tid] - v;
            g_rowptr[i] = ex;
            g_cursor[i] = ex;
        }
        __syncthreads();
        if (tid == 1023) soff = off + sh[1023];
        __syncthreads();
    }
    if (tid == 0) g_rowptr[NN] = soff;
}

__global__ void k_fill(const int* __restrict__ src, const int* __restrict__ tgt,
                       const float* __restrict__ w) {
    int e = blockIdx.x * blockDim.x + threadIdx.x;
    if (e >= EE) return;
    int slot = atomicAdd(&g_cursor[tgt[e]], 1);
    g_csrsrc[slot] = src[e];
    g_csrw[slot]  = w[e];
}

// ==================== layer 0 dense: s = x @ W0 + b0 ====================
// block 256 threads = 16x16, 64 nodes/block, 4x4 register micro-tile.
__global__ void k_mm0(const float* __restrict__ x, const float* __restrict__ W0,
                      const float* __restrict__ b0) {
    __shared__ float Wsh[NF * CH];   // 128*64 floats = 32KB
    int tid = threadIdx.x;
    for (int i = tid; i < NF * CH; i += 256) Wsh[i] = W0[i];
    __syncthreads();

    int base = blockIdx.x * 64;
    int ty = tid >> 4, tx = tid & 15;
    int c0 = tx * 4;

    float acc[4][4];
#pragma unroll
    for (int i = 0; i < 4; i++) {
        acc[i][0] = b0[c0 + 0]; acc[i][1] = b0[c0 + 1];
        acc[i][2] = b0[c0 + 2]; acc[i][3] = b0[c0 + 3];
    }
    const float* xr[4];
#pragma unroll
    for (int i = 0; i < 4; i++) {
        int nd = base + ty + 16 * i;
        if (nd > NN - 1) nd = NN - 1;
        xr[i] = x + (size_t)nd * NF;
    }
    for (int k = 0; k < NF; k++) {
        float4 b4 = *(const float4*)&Wsh[k * CH + c0];
#pragma unroll
        for (int i = 0; i < 4; i++) {
            float a = xr[i][k];
            acc[i][0] += a * b4.x; acc[i][1] += a * b4.y;
            acc[i][2] += a * b4.z; acc[i][3] += a * b4.w;
        }
    }
#pragma unroll
    for (int i = 0; i < 4; i++) {
        int nd = base + ty + 16 * i;
        if (nd < NN) {
            *(float4*)&g_s[nd * CH + c0] =
                make_float4(acc[i][0], acc[i][1], acc[i][2], acc[i][3]);
        }
    }
}

// ==== ODE func dense part: s = concat([t, groupnorm(h + coef*k)]) @ W1 + b1 ====
__global__ void k_feval(float coef, float t,
                        const float* __restrict__ W1, const float* __restrict__ b1,
                        const float* __restrict__ gnw, const float* __restrict__ gnb) {
    __shared__ float Wsh[65 * CH];   // 16.25 KB
    __shared__ float gsh[64 * 66];   // 64 nodes x (1 + 64) padded to 66
    int tid = threadIdx.x;
    for (int i = tid; i < 65 * CH; i += 256) Wsh[i] = W1[i];

    int base = blockIdx.x * 64;
    // load h_eff = h + coef*k
    for (int i = tid; i < 64 * CH; i += 256) {
        int gidx = base * CH + i;
        float v = 0.f;
        if (gidx < NN * CH) {
            v = g_h[gidx];
            if (coef != 0.f) v += coef * g_k[gidx];
        }
        int node = i >> 6, c = i & 63;
        gsh[node * 66 + 1 + c] = v;
    }
    __syncthreads();
    // groupnorm: group size 2 -> pairwise. 64 nodes * 32 groups
    for (int gi = tid; gi < 64 * 32; gi += 256) {
        int node = gi >> 5, grp = gi & 31;
        float* p = &gsh[node * 66 + 1 + 2 * grp];
        float a = p[0], b = p[1];
        float d = 0.5f * (a - b);            // a - mu
        float r = rsqrtf(d * d + 1e-5f);     // var = d^2
        p[0] =  d * r * gnw[2 * grp]     + gnb[2 * grp];
        p[1] = -d * r * gnw[2 * grp + 1] + gnb[2 * grp + 1];
        if (grp == 0) gsh[node * 66] = t;
    }
    __syncthreads();

    int ty = tid >> 4, tx = tid & 15;
    int c0 = tx * 4;
    float4 bb = *(const float4*)&b1[c0];
    float acc[4][4];
#pragma unroll
    for (int i = 0; i < 4; i++) {
        acc[i][0] = bb.x; acc[i][1] = bb.y; acc[i][2] = bb.z; acc[i][3] = bb.w;
    }
    for (int k = 0; k < 65; k++) {
        float4 w4 = *(const float4*)&Wsh[k * CH + c0];
#pragma unroll
        for (int i = 0; i < 4; i++) {
            float a = gsh[(ty + 16 * i) * 66 + k];
            acc[i][0] += a * w4.x; acc[i][1] += a * w4.y;
            acc[i][2] += a * w4.z; acc[i][3] += a * w4.w;
        }
    }
#pragma unroll
    for (int i = 0; i < 4; i++) {
        int nd = base + ty + 16 * i;
        if (nd < NN) {
            *(float4*)&g_s[nd * CH + c0] =
                make_float4(acc[i][0], acc[i][1], acc[i][2], acc[i][3]);
        }
    }
}

// ======================= SpMM aggregation (64 cols) =======================
// warp per row; lane handles column pair (2l, 2l+1).
// mode 0: g_h  = relu(agg)                      (layer 0)
// mode 1: g_k  = relu(agg); g_acc  = wacc * k   (k1)
// mode 2: g_k  = relu(agg); g_acc += wacc * k   (k2, k3)
// mode 3: g_h += g_acc + wacc * relu(agg)       (k4, RK4 state update)
__global__ void k_spmm(int mode, float wacc) {
    int row = (blockIdx.x * blockDim.x + threadIdx.x) >> 5;
    if (row >= NN) return;
    int lane = threadIdx.x & 31;
    int beg = g_rowptr[row], end = g_rowptr[row + 1];
    float ax = 0.f, ay = 0.f;
    for (int j = beg; j < end; j += 32) {
        int idx = j + lane;
        int sv = 0; float wv = 0.f;
        if (idx < end) { sv = g_csrsrc[idx]; wv = g_csrw[idx]; }
        int cnt = min(32, end - j);
        for (int q = 0; q < cnt; q++) {
            int   sq = __shfl_sync(0xffffffffu, sv, q);
            float wq = __shfl_sync(0xffffffffu, wv, q);
            float2 sr = *(const float2*)&g_s[sq * CH + 2 * lane];
            ax += wq * sr.x; ay += wq * sr.y;
        }
    }
    int o = row * CH + 2 * lane;
    float vx = fmaxf(ax, 0.f), vy = fmaxf(ay, 0.f);
    if (mode == 0) {
        g_h[o] = vx; g_h[o + 1] = vy;
    } else if (mode == 1) {
        g_k[o] = vx; g_k[o + 1] = vy;
        g_acc[o] = wacc * vx; g_acc[o + 1] = wacc * vy;
    } else if (mode == 2) {
        g_k[o] = vx; g_k[o + 1] = vy;
        g_acc[o] += wacc * vx; g_acc[o + 1] += wacc * vy;
    } else {
        g_h[o]     += g_acc[o]     + wacc * vx;
        g_h[o + 1] += g_acc[o + 1] + wacc * vy;
    }
}

// ================ final dense: s = h @ W2 + b2 (64 -> 40, padded stride 64) ================
__global__ void k_mm2(const float* __restrict__ W2, const float* __restrict__ b2) {
    int node = (blockIdx.x * blockDim.x + threadIdx.x) >> 5;
    if (node >= NN) return;
    int lane = threadIdx.x & 31;
    float hx = g_h[node * CH + 2 * lane];
    float hy = g_h[node * CH + 2 * lane + 1];
    float ax = 0.f, ay = 0.f;
    if (lane < 20) { ax = b2[2 * lane]; ay = b2[2 * lane + 1]; }
    for (int k = 0; k < CH; k++) {
        float hk = __shfl_sync(0xffffffffu, (k & 1) ? hy : hx, k >> 1);
        if (lane < 20) {
            ax += hk * W2[k * NC + 2 * lane];
            ay += hk * W2[k * NC + 2 * lane + 1];
        }
    }
    if (lane < 20) {
        g_s[node * CH + 2 * lane]     = ax;
        g_s[node * CH + 2 * lane + 1] = ay;
    }
}

// ============ final SpMM (40 cols) + log_softmax, writes d_out ============
__global__ void k_spmm40(float* __restrict__ out) {
    int row = (blockIdx.x * blockDim.x + threadIdx.x) >> 5;
    if (row >= NN) return;
    int lane = threadIdx.x & 31;
    int beg = g_rowptr[row], end = g_rowptr[row + 1];
    float ax = 0.f, ay = 0.f;
    for (int j = beg; j < end; j += 32) {
        int idx = j + lane;
        int sv = 0; float wv = 0.f;
        if (idx < end) { sv = g_csrsrc[idx]; wv = g_csrw[idx]; }
        int cnt = min(32, end - j);
        for (int q = 0; q < cnt; q++) {
            int   sq = __shfl_sync(0xffffffffu, sv, q);
            float wq = __shfl_sync(0xffffffffu, wv, q);
            if (lane < 20) {
                float2 sr = *(const float2*)&g_s[sq * CH + 2 * lane];
                ax += wq * sr.x; ay += wq * sr.y;
            }
        }
    }
    // log_softmax over 40 values held in lanes 0..19 (2 each)
    float NEG_INF = __int_as_float(0xff800000);
    float m = (lane < 20) ? fmaxf(ax, ay) : NEG_INF;
#pragma unroll
    for (int o = 16; o; o >>= 1) m = fmaxf(m, __shfl_xor_sync(0xffffffffu, m, o));
    float se = (lane < 20) ? (__expf(ax - m) + __expf(ay - m)) : 0.f;
    // use accurate expf for safety
    se = (lane < 20) ? (expf(ax - m) + expf(ay - m)) : 0.f;
#pragma unroll
    for (int o = 16; o; o >>= 1) se += __shfl_xor_sync(0xffffffffu, se, o);
    float lse = m + logf(se);
    if (lane < 20) {
        out[row * NC + 2 * lane]     = ax - lse;
        out[row * NC + 2 * lane + 1] = ay - lse;
    }
}

// =============================== driver ===============================
extern "C" void kernel_launch(void* const* d_in, const int* in_sizes, int n_in,
                              void* d_out, int out_size) {
    const float* x   = (const float*)d_in[0];
    const int*   src = (const int*)  d_in[1];
    const int*   tgt = (const int*)  d_in[2];
    const float* mw  = (const float*)d_in[3];
    const float* W0  = (const float*)d_in[4];
    const float* b0  = (const float*)d_in[5];
    const float* gnw = (const float*)d_in[6];
    const float* gnb = (const float*)d_in[7];
    const float* W1  = (const float*)d_in[8];
    const float* b1  = (const float*)d_in[9];
    const float* W2  = (const float*)d_in[10];
    const float* b2  = (const float*)d_in[11];
    float* out = (float*)d_out;
    (void)in_sizes; (void)n_in; (void)out_size;

    // CSR build (per call; no caching)
    k_zero_cnt<<<(NN + 255) / 256, 256>>>();
    k_hist<<<(EE + 255) / 256, 256>>>(tgt);
    k_scan<<<1, 1024>>>();
    k_fill<<<(EE + 255) / 256, 256>>>(src, tgt, mw);

    const int MMB   = (NN + 63) / 64;            // dense tiled blocks
    const int SPB   = (NN * 32 + 255) / 256;     // warp-per-row blocks

    // layer 0
    k_mm0<<<MMB, 256>>>(x, W0, b0);
    k_spmm<<<SPB, 256>>>(0, 0.f);

    // RK4: 4 steps, dt = 0.25
    const float dt = 0.25f;
    for (int st = 0; st < 4; st++) {
        float t0 = st * dt;
        k_feval<<<MMB, 256>>>(0.f,       t0,            W1, b1, gnw, gnb);
        k_spmm <<<SPB, 256>>>(1, dt / 6.f);
        k_feval<<<MMB, 256>>>(dt * 0.5f, t0 + dt * 0.5f, W1, b1, gnw, gnb);
        k_spmm <<<SPB, 256>>>(2, dt / 3.f);
        k_feval<<<MMB, 256>>>(dt * 0.5f, t0 + dt * 0.5f, W1, b1, gnw, gnb);
        k_spmm <<<SPB, 256>>>(2, dt / 3.f);
        k_feval<<<MMB, 256>>>(dt,        t0 + dt,        W1, b1, gnw, gnb);
        k_spmm <<<SPB, 256>>>(3, dt / 6.f);
    }

    // output layer
    k_mm2<<<SPB, 256>>>(W2, b2);
    k_spmm40<<<SPB, 256>>>(out);
}

// round 2
// speedup vs baseline: 1.1608x; 1.1608x over previous
#include <cuda_runtime.h>
#include <cuda_bf16.h>
#include <math.h>

#define NN 100000
#define EE 1600000
#define CH 64      // NHID
#define NF 128     // NFEAT
#define NC 40      // NCLASS
#define SCAN_B 1024
#define NB_SCAN ((NN + SCAN_B - 1) / SCAN_B)   // 98

// ---- scratch (static device globals; no allocation) ----
__device__ float g_h[NN * CH];
__device__ float g_k[NN * CH];
__device__ float g_acc[NN * CH];
__device__ float g_s[NN * CH];     // also holds final 40-col result padded to 64
__device__ int   g_rowptr[NN + 1];
__device__ int   g_cursor[NN];
__device__ int   g_cnt[NN];
__device__ int   g_bsum[128];
__device__ int   g_csrsrc[EE];
__device__ float g_csrw[EE];

// ============================ CSR build ============================
__global__ void k_zero_cnt() {
    int i = blockIdx.x * blockDim.x + threadIdx.x;
    if (i < NN) g_cnt[i] = 0;
}

__global__ void k_hist(const int* __restrict__ tgt) {
    int e = blockIdx.x * blockDim.x + threadIdx.x;
    if (e < EE) atomicAdd(&g_cnt[tgt[e]], 1);
}

// pass 1: per-block reduce of counts
__global__ void k_scan1() {
    __shared__ int sh[SCAN_B];
    int i = blockIdx.x * SCAN_B + threadIdx.x;
    sh[threadIdx.x] = (i < NN) ? g_cnt[i] : 0;
    __syncthreads();
    for (int d = SCAN_B / 2; d; d >>= 1) {
        if (threadIdx.x < d) sh[threadIdx.x] += sh[threadIdx.x + d];
        __syncthreads();
    }
    if (threadIdx.x == 0) g_bsum[blockIdx.x] = sh[0];
}

// pass 2: single-block exclusive scan of the 98 block sums
__global__ void k_scan2() {
    __shared__ int sh[128];
    int v = (threadIdx.x < NB_SCAN) ? g_bsum[threadIdx.x] : 0;
    sh[threadIdx.x] = v;
    __syncthreads();
    for (int d = 1; d < 128; d <<= 1) {
        int t = (threadIdx.x >= d) ? sh[threadIdx.x - d] : 0;
        __syncthreads();
        sh[threadIdx.x] += t;
        __syncthreads();
    }
    if (threadIdx.x < NB_SCAN) g_bsum[threadIdx.x] = sh[threadIdx.x] - v;  // exclusive
    if (threadIdx.x == NB_SCAN - 1) g_rowptr[NN] = sh[threadIdx.x];
}

// pass 3: block-local exclusive scan + block offset
__global__ void k_scan3() {
    __shared__ int sh[SCAN_B];
    int i = blockIdx.x * SCAN_B + threadIdx.x;
    int v = (i < NN) ? g_cnt[i] : 0;
    sh[threadIdx.x] = v;
    __syncthreads();
    for (int d = 1; d < SCAN_B; d <<= 1) {
        int t = (threadIdx.x >= d) ? sh[threadIdx.x - d] : 0;
        __syncthreads();
        sh[threadIdx.x] += t;
        __syncthreads();
    }
    if (i < NN) {
        int ex = g_bsum[blockIdx.x] + sh[threadIdx.x] - v;
        g_rowptr[i] = ex;
        g_cursor[i] = ex;
    }
}

__global__ void k_fill(const int* __restrict__ src, const int* __restrict__ tgt,
                       const float* __restrict__ w) {
    int e = blockIdx.x * blockDim.x + threadIdx.x;
    if (e >= EE) return;
    int slot = atomicAdd(&g_cursor[tgt[e]], 1);
    g_csrsrc[slot] = src[e];
    g_csrw[slot]  = w[e];
}

// ==================== layer 0 dense: s = x @ W0 + b0 ====================
// block 256 threads = 16x16, 64 nodes/block, 4x4 register micro-tile, float4 x loads.
__global__ void k_mm0(const float* __restrict__ x, const float* __restrict__ W0,
                      const float* __restrict__ b0) {
    __shared__ float Wsh[NF * CH];   // 32KB
    int tid = threadIdx.x;
    for (int i = tid; i < NF * CH; i += 256) Wsh[i] = W0[i];
    __syncthreads();

    int base = blockIdx.x * 64;
    int ty = tid >> 4, tx = tid & 15;
    int c0 = tx * 4;

    float acc[4][4];
#pragma unroll
    for (int i = 0; i < 4; i++) {
        acc[i][0] = b0[c0 + 0]; acc[i][1] = b0[c0 + 1];
        acc[i][2] = b0[c0 + 2]; acc[i][3] = b0[c0 + 3];
    }
    const float* xr[4];
#pragma unroll
    for (int i = 0; i < 4; i++) {
        int nd = base + ty + 16 * i;
        if (nd > NN - 1) nd = NN - 1;
        xr[i] = x + (size_t)nd * NF;
    }
    for (int k = 0; k < NF; k += 4) {
        float4 a4[4];
#pragma unroll
        for (int i = 0; i < 4; i++) a4[i] = *(const float4*)&xr[i][k];
#pragma unroll
        for (int kk = 0; kk < 4; kk++) {
            float4 b4 = *(const float4*)&Wsh[(k + kk) * CH + c0];
#pragma unroll
            for (int i = 0; i < 4; i++) {
                float a = (kk == 0) ? a4[i].x : (kk == 1) ? a4[i].y : (kk == 2) ? a4[i].z : a4[i].w;
                acc[i][0] += a * b4.x; acc[i][1] += a * b4.y;
                acc[i][2] += a * b4.z; acc[i][3] += a * b4.w;
            }
        }
    }
#pragma unroll
    for (int i = 0; i < 4; i++) {
        int nd = base + ty + 16 * i;
        if (nd < NN) {
            *(float4*)&g_s[nd * CH + c0] =
                make_float4(acc[i][0], acc[i][1], acc[i][2], acc[i][3]);
        }
    }
}

// ==== ODE func dense part: s = concat([t, groupnorm(h + coef*k)]) @ W1 + b1 ====
// 128 nodes per block (halves W1 L2 traffic vs 64), 8x4 register tile.
#define NPB 128
__global__ void k_feval(float coef, float t,
                        const float* __restrict__ W1, const float* __restrict__ b1,
                        const float* __restrict__ gnw, const float* __restrict__ gnb) {
    __shared__ float Wsh[65 * CH];    // 16.25 KB
    __shared__ float gsh[NPB * 66];   // 33 KB
    int tid = threadIdx.x;
    for (int i = tid; i < 65 * CH; i += 256) Wsh[i] = W1[i];

    int base = blockIdx.x * NPB;
    for (int i = tid; i < NPB * CH; i += 256) {
        int node = i >> 6, c = i & 63;
        int g = base + node;
        float v = 0.f;
        if (g < NN) {
            int gi = g * CH + c;
            v = g_h[gi] + coef * g_k[gi];   // g_k zero-init before first use
        }
        gsh[node * 66 + 1 + c] = v;
    }
    __syncthreads();
    // groupnorm: group size 2 -> pairwise closed form
    for (int gi = tid; gi < NPB * 32; gi += 256) {
        int node = gi >> 5, grp = gi & 31;
        float* p = &gsh[node * 66 + 1 + 2 * grp];
        float a = p[0], b = p[1];
        float d = 0.5f * (a - b);            // a - mu
        float r = rsqrtf(d * d + 1e-5f);     // var = d^2
        p[0] =  d * r * gnw[2 * grp]     + gnb[2 * grp];
        p[1] = -d * r * gnw[2 * grp + 1] + gnb[2 * grp + 1];
        if (grp == 0) gsh[node * 66] = t;
    }
    __syncthreads();

    int ty = tid >> 4, tx = tid & 15;
    int c0 = tx * 4;
    float4 bb = *(const float4*)&b1[c0];
    float acc[8][4];
#pragma unroll
    for (int i = 0; i < 8; i++) {
        acc[i][0] = bb.x; acc[i][1] = bb.y; acc[i][2] = bb.z; acc[i][3] = bb.w;
    }
    for (int k = 0; k < 65; k++) {
        float4 w4 = *(const float4*)&Wsh[k * CH + c0];
#pragma unroll
        for (int i = 0; i < 8; i++) {
            float a = gsh[(ty + 16 * i) * 66 + k];
            acc[i][0] += a * w4.x; acc[i][1] += a * w4.y;
            acc[i][2] += a * w4.z; acc[i][3] += a * w4.w;
        }
    }
#pragma unroll
    for (int i = 0; i < 8; i++) {
        int nd = base + ty + 16 * i;
        if (nd < NN) {
            *(float4*)&g_s[nd * CH + c0] =
                make_float4(acc[i][0], acc[i][1], acc[i][2], acc[i][3]);
        }
    }
}

// ======================= SpMM aggregation (64 cols) =======================
// warp per row; lane handles column pair (2l, 2l+1). Inner loop unrolled x4
// for MLP=4 (previous version serialized on L2 latency per edge).
// mode 0: g_h  = relu(agg)
// mode 1: g_k  = relu(agg); g_acc  = wacc * k
// mode 2: g_k  = relu(agg); g_acc += wacc * k
// mode 3: g_h += g_acc + wacc * relu(agg)       (RK4 state update)
__global__ void k_spmm(int mode, float wacc) {
    int row = (blockIdx.x * blockDim.x + threadIdx.x) >> 5;
    if (row >= NN) return;
    int lane = threadIdx.x & 31;
    int beg = g_rowptr[row], end = g_rowptr[row + 1];
    float ax = 0.f, ay = 0.f;
    for (int j = beg; j < end; j += 32) {
        int idx = j + lane;
        int sv = 0; float wv = 0.f;
        if (idx < end) { sv = g_csrsrc[idx]; wv = g_csrw[idx]; }
        int cnt4 = (min(32, end - j) + 3) & ~3;   // pad to 4; padded lanes have wv=0, sv=0 (valid row)
        for (int q = 0; q < cnt4; q += 4) {
            int   s0 = __shfl_sync(0xffffffffu, sv, q);
            int   s1 = __shfl_sync(0xffffffffu, sv, q + 1);
            int   s2 = __shfl_sync(0xffffffffu, sv, q + 2);
            int   s3 = __shfl_sync(0xffffffffu, sv, q + 3);
            float w0 = __shfl_sync(0xffffffffu, wv, q);
            float w1 = __shfl_sync(0xffffffffu, wv, q + 1);
            float w2 = __shfl_sync(0xffffffffu, wv, q + 2);
            float w3 = __shfl_sync(0xffffffffu, wv, q + 3);
            float2 r0 = *(const float2*)&g_s[s0 * CH + 2 * lane];
            float2 r1 = *(const float2*)&g_s[s1 * CH + 2 * lane];
            float2 r2 = *(const float2*)&g_s[s2 * CH + 2 * lane];
            float2 r3 = *(const float2*)&g_s[s3 * CH + 2 * lane];
            ax += w0 * r0.x; ay += w0 * r0.y;
            ax += w1 * r1.x; ay += w1 * r1.y;
            ax += w2 * r2.x; ay += w2 * r2.y;
            ax += w3 * r3.x; ay += w3 * r3.y;
        }
    }
    int o = row * CH + 2 * lane;
    float vx = fmaxf(ax, 0.f), vy = fmaxf(ay, 0.f);
    if (mode == 0) {
        g_h[o] = vx; g_h[o + 1] = vy;
    } else if (mode == 1) {
        g_k[o] = vx; g_k[o + 1] = vy;
        g_acc[o] = wacc * vx; g_acc[o + 1] = wacc * vy;
    } else if (mode == 2) {
        g_k[o] = vx; g_k[o + 1] = vy;
        g_acc[o] += wacc * vx; g_acc[o + 1] += wacc * vy;
    } else {
        g_h[o]     += g_acc[o]     + wacc * vx;
        g_h[o + 1] += g_acc[o + 1] + wacc * vy;
    }
}

// ================ final dense: s = h @ W2 + b2 (64 -> 40, padded stride 64) ================
__global__ void k_mm2(const float* __restrict__ W2, const float* __restrict__ b2) {
    int node = (blockIdx.x * blockDim.x + threadIdx.x) >> 5;
    if (node >= NN) return;
    int lane = threadIdx.x & 31;
    float hx = g_h[node * CH + 2 * lane];
    float hy = g_h[node * CH + 2 * lane + 1];
    float ax = 0.f, ay = 0.f;
    if (lane < 20) { ax = b2[2 * lane]; ay = b2[2 * lane + 1]; }
    for (int k = 0; k < CH; k++) {
        float hk = __shfl_sync(0xffffffffu, (k & 1) ? hy : hx, k >> 1);
        if (lane < 20) {
            ax += hk * W2[k * NC + 2 * lane];
            ay += hk * W2[k * NC + 2 * lane + 1];
        }
    }
    if (lane < 20) {
        g_s[node * CH + 2 * lane]     = ax;
        g_s[node * CH + 2 * lane + 1] = ay;
    }
}

// ============ final SpMM (40 cols) + log_softmax, writes d_out ============
__global__ void k_spmm40(float* __restrict__ out) {
    int row = (blockIdx.x * blockDim.x + threadIdx.x) >> 5;
    if (row >= NN) return;
    int lane = threadIdx.x & 31;
    int beg = g_rowptr[row], end = g_rowptr[row + 1];
    float ax = 0.f, ay = 0.f;
    for (int j = beg; j < end; j += 32) {
        int idx = j + lane;
        int sv = 0; float wv = 0.f;
        if (idx < end) { sv = g_csrsrc[idx]; wv = g_csrw[idx]; }
        int cnt4 = (min(32, end - j) + 3) & ~3;
        for (int q = 0; q < cnt4; q += 4) {
            int   s0 = __shfl_sync(0xffffffffu, sv, q);
            int   s1 = __shfl_sync(0xffffffffu, sv, q + 1);
            int   s2 = __shfl_sync(0xffffffffu, sv, q + 2);
            int   s3 = __shfl_sync(0xffffffffu, sv, q + 3);
            float w0 = __shfl_sync(0xffffffffu, wv, q);
            float w1 = __shfl_sync(0xffffffffu, wv, q + 1);
            float w2 = __shfl_sync(0xffffffffu, wv, q + 2);
            float w3 = __shfl_sync(0xffffffffu, wv, q + 3);
            if (lane < 20) {
                float2 r0 = *(const float2*)&g_s[s0 * CH + 2 * lane];
                float2 r1 = *(const float2*)&g_s[s1 * CH + 2 * lane];
                float2 r2 = *(const float2*)&g_s[s2 * CH + 2 * lane];
                float2 r3 = *(const float2*)&g_s[s3 * CH + 2 * lane];
                ax += w0 * r0.x; ay += w0 * r0.y;
                ax += w1 * r1.x; ay += w1 * r1.y;
                ax += w2 * r2.x; ay += w2 * r2.y;
                ax += w3 * r3.x; ay += w3 * r3.y;
            }
        }
    }
    // log_softmax over 40 values held in lanes 0..19 (2 each)
    float NEG_INF = __int_as_float(0xff800000);
    float m = (lane < 20) ? fmaxf(ax, ay) : NEG_INF;
#pragma unroll
    for (int o = 16; o; o >>= 1) m = fmaxf(m, __shfl_xor_sync(0xffffffffu, m, o));
    float se = (lane < 20) ? (expf(ax - m) + expf(ay - m)) : 0.f;
#pragma unroll
    for (int o = 16; o; o >>= 1) se += __shfl_xor_sync(0xffffffffu, se, o);
    float lse = m + logf(se);
    if (lane < 20) {
        out[row * NC + 2 * lane]     = ax - lse;
        out[row * NC + 2 * lane + 1] = ay - lse;
    }
}

// =============================== driver ===============================
extern "C" void kernel_launch(void* const* d_in, const int* in_sizes, int n_in,
                              void* d_out, int out_size) {
    const float* x   = (const float*)d_in[0];
    const int*   src = (const int*)  d_in[1];
    const int*   tgt = (const int*)  d_in[2];
    const float* mw  = (const float*)d_in[3];
    const float* W0  = (const float*)d_in[4];
    const float* b0  = (const float*)d_in[5];
    const float* gnw = (const float*)d_in[6];
    const float* gnb = (const float*)d_in[7];
    const float* W1  = (const float*)d_in[8];
    const float* b1  = (const float*)d_in[9];
    const float* W2  = (const float*)d_in[10];
    const float* b2  = (const float*)d_in[11];
    float* out = (float*)d_out;
    (void)in_sizes; (void)n_in; (void)out_size;

    // CSR build (per call; no caching)
    k_zero_cnt<<<(NN + 255) / 256, 256>>>();
    k_hist<<<(EE + 255) / 256, 256>>>(tgt);
    k_scan1<<<NB_SCAN, SCAN_B>>>();
    k_scan2<<<1, 128>>>();
    k_scan3<<<NB_SCAN, SCAN_B>>>();
    k_fill<<<(EE + 255) / 256, 256>>>(src, tgt, mw);

    const int MMB0  = (NN + 63) / 64;            // mm0 blocks
    const int FEB   = (NN + NPB - 1) / NPB;      // feval blocks
    const int SPB   = (NN * 32 + 255) / 256;     // warp-per-row blocks

    // layer 0
    k_mm0<<<MMB0, 256>>>(x, W0, b0);
    k_spmm<<<SPB, 256>>>(0, 0.f);

    // RK4: 4 steps, dt = 0.25
    const float dt = 0.25f;
    for (int st = 0; st < 4; st++) {
        float t0 = st * dt;
        k_feval<<<FEB, 256>>>(0.f,        t0,             W1, b1, gnw, gnb);
        k_spmm <<<SPB, 256>>>(1, dt / 6.f);
        k_feval<<<FEB, 256>>>(dt * 0.5f,  t0 + dt * 0.5f, W1, b1, gnw, gnb);
        k_spmm <<<SPB, 256>>>(2, dt / 3.f);
        k_feval<<<FEB, 256>>>(dt * 0.5f,  t0 + dt * 0.5f, W1, b1, gnw, gnb);
        k_spmm <<<SPB, 256>>>(2, dt / 3.f);
        k_feval<<<FEB, 256>>>(dt,         t0 + dt,        W1, b1, gnw, gnb);
        k_spmm <<<SPB, 256>>>(3, dt / 6.f);
    }

    // output layer
    k_mm2<<<SPB, 256>>>(W2, b2);
    k_spmm40<<<SPB, 256>>>(out);
}